// round 2
// baseline (speedup 1.0000x reference)
#include <cuda_runtime.h>
#include <math.h>

// GRU decoder: B=2048, H=512, F=128, T=96.
// Recurrence folded to a single GEMM per step via W2 = w_ih @ fc_w:
//   for t>=1: gi_t = h_t @ W2^T + (w_ih@fc_b + b_ih)
// Packed gate weight G (N=2048, K=512), column n = 4*j + gate:
//   gate 0: W2_r[j] + w_hh_r[j]   (pre_r = i_r + h_r)
//   gate 1: W2_z[j] + w_hh_z[j]   (pre_z = i_z + h_z)
//   gate 2: W2_n[j]               (i_n)
//   gate 3: w_hh_n[j]             (h_n)
// Step 0 uses x=0 -> G0 built from w_hh only (i_n column = 0, bias = b_ih_n).
// Output x_new of step s = h_{s+1} @ fc_w^T + fc_b, written to out[:, 95-s, :].
// Fused into the NEXT step's kernel as 8 extra blocks (reads same h input).

#define Bsz 2048
#define Hsz 512
#define Fsz 128
#define Tsz 96
#define Ksz 512
#define NGc 2048

__device__ float g_G [NGc * Ksz];
__device__ float g_G0[NGc * Ksz];
__device__ float g_bias [NGc];
__device__ float g_bias0[NGc];
__device__ float g_h[2][Bsz * Hsz];

__global__ void copy_h0_kernel(const float* __restrict__ hidden) {
    int i = blockIdx.x * blockDim.x + threadIdx.x;
    ((float4*)g_h[0])[i] = ((const float4*)hidden)[i];
}

// One block per source row r in [0, 1536): computes W2[r,:] = w_ih[r,:] @ fc_w
// and scatters into packed G/G0 + biases.
__global__ void precompute_kernel(const float* __restrict__ w_ih,
                                  const float* __restrict__ w_hh,
                                  const float* __restrict__ b_ih,
                                  const float* __restrict__ b_hh,
                                  const float* __restrict__ fc_w,
                                  const float* __restrict__ fc_b) {
    int r = blockIdx.x;     // 0..1535
    int k = threadIdx.x;    // 0..511
    __shared__ float sw[Fsz];
    __shared__ float sb[Fsz];
    if (k < Fsz) { sw[k] = w_ih[r * Fsz + k]; sb[k] = fc_b[k]; }
    __syncthreads();
    float acc = 0.f;
    #pragma unroll 8
    for (int f = 0; f < Fsz; f++) acc += sw[f] * fc_w[f * Ksz + k];
    float whh = w_hh[r * Ksz + k];
    int j = r & (Hsz - 1);
    int band = r >> 9;      // 0=r-gate rows, 1=z, 2=n
    if (band == 0) {
        g_G [(4*j+0)*Ksz + k] = acc + whh;
        g_G0[(4*j+0)*Ksz + k] = whh;
    } else if (band == 1) {
        g_G [(4*j+1)*Ksz + k] = acc + whh;
        g_G0[(4*j+1)*Ksz + k] = whh;
    } else {
        g_G [(4*j+2)*Ksz + k] = acc;     // i_n weights
        g_G0[(4*j+2)*Ksz + k] = 0.f;     // x=0 at t=0
        g_G [(4*j+3)*Ksz + k] = whh;     // h_n weights
        g_G0[(4*j+3)*Ksz + k] = whh;
    }
    if (k == 0) {
        float b2 = 0.f;
        for (int f = 0; f < Fsz; f++) b2 += sw[f] * sb[f];   // (w_ih @ fc_b)[r]
        float bih = b_ih[r], bhh = b_hh[r];
        if (band == 0) { g_bias[4*j+0] = b2 + bih + bhh; g_bias0[4*j+0] = bih + bhh; }
        else if (band == 1) { g_bias[4*j+1] = b2 + bih + bhh; g_bias0[4*j+1] = bih + bhh; }
        else {
            g_bias [4*j+2] = b2 + bih;  g_bias0[4*j+2] = bih;
            g_bias [4*j+3] = bhh;       g_bias0[4*j+3] = bhh;
        }
    }
}

// Fused step kernel. Tile: BM=256, BN=128, BK=16, 512 threads, 8x8/thread.
// Blocks [0, ngate): gate GEMM C = h @ G^T + gate epilogue -> h_next.
// Blocks [ngate, ...): out GEMM  h @ fc_w^T + fc_b -> out[:, trow, :].
__global__ __launch_bounds__(512, 1)
void step_kernel(int pp, int use_g0,
                 const float* __restrict__ fcw, const float* __restrict__ fcb,
                 float* __restrict__ outp, int trow, int ngate)
{
    const float* __restrict__ hin = g_h[pp];
    float* __restrict__ hout = g_h[pp ^ 1];

    const bool outmode = ((int)blockIdx.x >= ngate);
    int bid = outmode ? ((int)blockIdx.x - ngate) : (int)blockIdx.x;
    int row_tile, n0;
    const float* __restrict__ Bmat;
    if (outmode) { row_tile = bid; n0 = 0; Bmat = fcw; }
    else {
        row_tile = bid >> 4;
        n0 = (bid & 15) * 128;
        Bmat = use_g0 ? g_G0 : g_G;
    }
    const int m0 = row_tile * 256;

    __shared__ float As[2][16][256];
    __shared__ float Bs[2][16][128];

    const int tid = threadIdx.x;
    const int tx = tid & 15;
    const int ty = tid >> 4;

    // A: 256x16 tile = 1024 float4 -> 2 per thread (stored transposed [k][m])
    const int la0 = tid * 2;
    const int am0 = la0 >> 2, ak0 = (la0 & 3) << 2;
    const int la1 = la0 + 1;
    const int am1 = la1 >> 2, ak1 = (la1 & 3) << 2;
    const float* Ag0 = hin + (m0 + am0) * Ksz + ak0;
    const float* Ag1 = hin + (m0 + am1) * Ksz + ak1;
    // B: 128x16 tile = 512 float4 -> 1 per thread
    const int bn = tid >> 2, bk = (tid & 3) << 2;
    const float* Bg = Bmat + (n0 + bn) * Ksz + bk;

    float c[8][8];
    #pragma unroll
    for (int i = 0; i < 8; i++)
        #pragma unroll
        for (int q = 0; q < 8; q++) c[i][q] = 0.f;

    float4 pa0 = *(const float4*)Ag0;
    float4 pa1 = *(const float4*)Ag1;
    float4 pb  = *(const float4*)Bg;

    int buf = 0;
    As[0][ak0+0][am0]=pa0.x; As[0][ak0+1][am0]=pa0.y; As[0][ak0+2][am0]=pa0.z; As[0][ak0+3][am0]=pa0.w;
    As[0][ak1+0][am1]=pa1.x; As[0][ak1+1][am1]=pa1.y; As[0][ak1+2][am1]=pa1.z; As[0][ak1+3][am1]=pa1.w;
    Bs[0][bk+0][bn]=pb.x; Bs[0][bk+1][bn]=pb.y; Bs[0][bk+2][bn]=pb.z; Bs[0][bk+3][bn]=pb.w;
    __syncthreads();

    const int NKT = Ksz / 16;   // 32
    for (int kt = 0; kt < NKT; kt++) {
        if (kt + 1 < NKT) {
            const int off = (kt + 1) * 16;
            pa0 = *(const float4*)(Ag0 + off);
            pa1 = *(const float4*)(Ag1 + off);
            pb  = *(const float4*)(Bg  + off);
        }
        #pragma unroll
        for (int kk = 0; kk < 16; kk++) {
            float4 a0 = *(const float4*)&As[buf][kk][ty * 4];
            float4 a1 = *(const float4*)&As[buf][kk][128 + ty * 4];
            float4 b0 = *(const float4*)&Bs[buf][kk][tx * 4];
            float4 b1 = *(const float4*)&Bs[buf][kk][64 + tx * 4];
            float a[8]  = {a0.x, a0.y, a0.z, a0.w, a1.x, a1.y, a1.z, a1.w};
            float bb[8] = {b0.x, b0.y, b0.z, b0.w, b1.x, b1.y, b1.z, b1.w};
            #pragma unroll
            for (int i = 0; i < 8; i++)
                #pragma unroll
                for (int q = 0; q < 8; q++)
                    c[i][q] += a[i] * bb[q];
        }
        if (kt + 1 < NKT) {
            buf ^= 1;
            As[buf][ak0+0][am0]=pa0.x; As[buf][ak0+1][am0]=pa0.y; As[buf][ak0+2][am0]=pa0.z; As[buf][ak0+3][am0]=pa0.w;
            As[buf][ak1+0][am1]=pa1.x; As[buf][ak1+1][am1]=pa1.y; As[buf][ak1+2][am1]=pa1.z; As[buf][ak1+3][am1]=pa1.w;
            Bs[buf][bk+0][bn]=pb.x; Bs[buf][bk+1][bn]=pb.y; Bs[buf][bk+2][bn]=pb.z; Bs[buf][bk+3][bn]=pb.w;
            __syncthreads();
        }
    }

    if (!outmode) {
        const float* __restrict__ bias = use_g0 ? g_bias0 : g_bias;
        float bi[8];
        #pragma unroll
        for (int q = 0; q < 8; q++) {
            int nn = n0 + ((q < 4) ? (tx * 4 + q) : (64 + tx * 4 + (q - 4)));
            bi[q] = bias[nn];
        }
        const int jb = (n0 >> 2) + tx;   // first j handled by this thread
        #pragma unroll
        for (int i = 0; i < 8; i++) {
            int mrow = m0 + ((i < 4) ? (ty * 4 + i) : (128 + ty * 4 + (i - 4)));
            #pragma unroll
            for (int h2 = 0; h2 < 2; h2++) {
                int j = jb + h2 * 16;
                int o = h2 * 4;
                float pr = c[i][o + 0] + bi[o + 0];
                float pz = c[i][o + 1] + bi[o + 1];
                float pn = c[i][o + 2] + bi[o + 2];
                float ph = c[i][o + 3] + bi[o + 3];
                float rg = 1.f / (1.f + __expf(-pr));
                float zg = 1.f / (1.f + __expf(-pz));
                float ng = tanhf(pn + rg * ph);
                float hold = hin[mrow * Hsz + j];
                hout[mrow * Hsz + j] = (1.f - zg) * ng + zg * hold;
            }
        }
    } else {
        #pragma unroll
        for (int i = 0; i < 8; i++) {
            int mrow = m0 + ((i < 4) ? (ty * 4 + i) : (128 + ty * 4 + (i - 4)));
            float* orow = outp + (size_t)mrow * (Tsz * Fsz) + (size_t)trow * Fsz;
            #pragma unroll
            for (int q = 0; q < 8; q++) {
                int f = (q < 4) ? (tx * 4 + q) : (64 + tx * 4 + (q - 4));
                orow[f] = c[i][q] + fcb[f];
            }
        }
    }
}

extern "C" void kernel_launch(void* const* d_in, const int* in_sizes, int n_in,
                              void* d_out, int out_size) {
    (void)in_sizes; (void)n_in; (void)out_size;
    const float* hidden = (const float*)d_in[0];
    const float* w_ih   = (const float*)d_in[1];
    const float* w_hh   = (const float*)d_in[2];
    const float* b_ih   = (const float*)d_in[3];
    const float* b_hh   = (const float*)d_in[4];
    const float* fc_w   = (const float*)d_in[5];
    const float* fc_b   = (const float*)d_in[6];
    float* outp = (float*)d_out;

    copy_h0_kernel<<<(Bsz * Hsz / 4) / 256, 256>>>(hidden);
    precompute_kernel<<<3 * Hsz, Ksz>>>(w_ih, w_hh, b_ih, b_hh, fc_w, fc_b);

    // Step 0: x = 0, gate weights G0, no fused output (h_0 is not emitted).
    step_kernel<<<128, 512>>>(0, 1, fc_w, fc_b, outp, 0, 128);
    // Steps 1..95: gate GEMM for step t + output of step t-1 (from h_t) at row 96-t.
    for (int t = 1; t < Tsz; t++)
        step_kernel<<<136, 512>>>(t & 1, 0, fc_w, fc_b, outp, Tsz - t, 128);
    // Final output of step 95 from h_96 (parity 0), row 0. All blocks out-mode.
    step_kernel<<<8, 512>>>(0, 0, fc_w, fc_b, outp, 0, 0);
}

// round 4
// speedup vs baseline: 1.4127x; 1.4127x over previous
#include <cuda_runtime.h>
#include <cuda_bf16.h>
#include <math.h>
#include <stdint.h>

// GRU decoder B=2048,H=512,F=128,T=96 via legacy mma.sync (bf16 HMMA, fp32 acc).
// tcgen05 is unavailable: harness builds PTX for compute_103 (no 'a'), which
// rejects tcgen05.*. mma.sync/ldmatrix/cp.async are baseline-PTX and compile.
// Folding: W2 = w_ih@fc_w -> one GEMM/step: C = h_t @ G^T,
//   G packed (N=2048,K=512), col n=4j+g: [r_comb, z_comb, i_n, h_n].
// fp32 precision via 3-term bf16 split: C ~= Ah*Bh + Al*Bh + Ah*Bl.
// Output GEMM x = h@fc_w^T fused as 16 extra CTAs per step.

#define Bsz 2048
#define Hsz 512
#define Fsz 128
#define Tsz 96
#define NCHUNK 8          // K=512 / BK=64
#define STG 65536         // stage bytes: 4 operands x 16KB
#define SMEMB (3 * STG)

// ---- device globals ----
__device__ __nv_bfloat16 g_Gh [2048 * 512];
__device__ __nv_bfloat16 g_Gl [2048 * 512];
__device__ __nv_bfloat16 g_G0h[2048 * 512];
__device__ __nv_bfloat16 g_G0l[2048 * 512];
__device__ __nv_bfloat16 g_Fwh[128 * 512];
__device__ __nv_bfloat16 g_Fwl[128 * 512];
__device__ __nv_bfloat16 g_Ah[2][2048 * 512];
__device__ __nv_bfloat16 g_Al[2][2048 * 512];
__device__ float g_hf[2][2048 * 512];
__device__ float g_bias[2048];
__device__ float g_bias0[2048];

// ---- helpers ----
__device__ __forceinline__ uint32_t smem_u32(const void* p) {
    uint32_t a;
    asm("{ .reg .u64 t; cvta.to.shared.u64 t, %1; cvt.u32.u64 %0, t; }" : "=r"(a) : "l"(p));
    return a;
}
__device__ __forceinline__ void mma_bf16(float* d, const uint32_t* a, uint32_t b0, uint32_t b1) {
    asm volatile(
        "mma.sync.aligned.m16n8k16.row.col.f32.bf16.bf16.f32 "
        "{%0,%1,%2,%3}, {%4,%5,%6,%7}, {%8,%9}, {%0,%1,%2,%3};"
        : "+f"(d[0]), "+f"(d[1]), "+f"(d[2]), "+f"(d[3])
        : "r"(a[0]), "r"(a[1]), "r"(a[2]), "r"(a[3]), "r"(b0), "r"(b1));
}
__device__ __forceinline__ void ldm4(uint32_t* r, uint32_t addr) {
    asm volatile("ldmatrix.sync.aligned.m8n8.x4.shared.b16 {%0,%1,%2,%3}, [%4];"
                 : "=r"(r[0]), "=r"(r[1]), "=r"(r[2]), "=r"(r[3]) : "r"(addr));
}
__device__ __forceinline__ void cpa16(uint32_t s, const void* g) {
    asm volatile("cp.async.cg.shared.global [%0], [%1], 16;" :: "r"(s), "l"(g));
}
__device__ __forceinline__ void cpa_commit() { asm volatile("cp.async.commit_group;" ::: "memory"); }
__device__ __forceinline__ void cpa_wait1()  { asm volatile("cp.async.wait_group 1;"  ::: "memory"); }

__device__ __forceinline__ void put_split(__nv_bfloat16* H, __nv_bfloat16* L, int idx, float v) {
    __nv_bfloat16 h = __float2bfloat16(v);
    __nv_bfloat16 l = __float2bfloat16(v - __bfloat162float(h));
    H[idx] = h; L[idx] = l;
}

// ---- precompute: fold weights, split to bf16 hi/lo (plain row-major) ----
__global__ void precompute_kernel(const float* __restrict__ w_ih,
                                  const float* __restrict__ w_hh,
                                  const float* __restrict__ b_ih,
                                  const float* __restrict__ b_hh,
                                  const float* __restrict__ fc_w,
                                  const float* __restrict__ fc_b) {
    int r = blockIdx.x;   // 0..1535
    int k = threadIdx.x;  // 0..511
    __shared__ float sw[Fsz], sb[Fsz];
    if (k < Fsz) { sw[k] = w_ih[r * Fsz + k]; sb[k] = fc_b[k]; }
    __syncthreads();
    float acc = 0.f;
    #pragma unroll 8
    for (int f = 0; f < Fsz; f++) acc += sw[f] * fc_w[f * Hsz + k];
    float whh = w_hh[r * Hsz + k];
    int j = r & (Hsz - 1);
    int band = r >> 9;
    if (band == 0) {
        int o = (4 * j + 0) * Hsz + k;
        put_split(g_Gh, g_Gl, o, acc + whh);
        put_split(g_G0h, g_G0l, o, whh);
    } else if (band == 1) {
        int o = (4 * j + 1) * Hsz + k;
        put_split(g_Gh, g_Gl, o, acc + whh);
        put_split(g_G0h, g_G0l, o, whh);
    } else {
        int o2 = (4 * j + 2) * Hsz + k;
        put_split(g_Gh, g_Gl, o2, acc);
        put_split(g_G0h, g_G0l, o2, 0.f);
        int o3 = (4 * j + 3) * Hsz + k;
        put_split(g_Gh, g_Gl, o3, whh);
        put_split(g_G0h, g_G0l, o3, whh);
    }
    if (k == 0) {
        float b2 = 0.f;
        for (int f = 0; f < Fsz; f++) b2 += sw[f] * sb[f];
        float bih = b_ih[r], bhh = b_hh[r];
        if (band == 0) { g_bias[4*j+0] = b2 + bih + bhh; g_bias0[4*j+0] = bih + bhh; }
        else if (band == 1) { g_bias[4*j+1] = b2 + bih + bhh; g_bias0[4*j+1] = bih + bhh; }
        else {
            g_bias [4*j+2] = b2 + bih;  g_bias0[4*j+2] = bih;
            g_bias [4*j+3] = bhh;       g_bias0[4*j+3] = bhh;
        }
    }
}

__global__ void conv_fw_kernel(const float* __restrict__ fc_w) {
    int idx = blockIdx.x * blockDim.x + threadIdx.x;  // 128*512
    put_split(g_Fwh, g_Fwl, idx, fc_w[idx]);
}

__global__ void conv_h0_kernel(const float* __restrict__ hidden) {
    int idx = blockIdx.x * blockDim.x + threadIdx.x;  // 2048*512
    float v = hidden[idx];
    g_hf[0][idx] = v;
    put_split(g_Ah[0], g_Al[0], idx, v);
}

// ---- fused step kernel ----
// grid: ngate gate CTAs (mt = bx>>4, nt = bx&15) + out CTAs (mt = bx-ngate).
// BM=BN=128, BK=64, 256 threads, 8 warps: warp tile 64x32 (wm = (wid>>2)*64,
// wn = (wid&3)*32). SMEM stage: Ah|Al|Bh|Bl 16KB each, XOR-swizzled 16B units.
__global__ __launch_bounds__(256, 1)
void mma_step(int pp, int use0, int ngate, int tout,
              const float* __restrict__ fcb, float* __restrict__ outp) {
    extern __shared__ unsigned char smraw[];
    const uint32_t sb = smem_u32(smraw);

    const int tid = threadIdx.x, wid = tid >> 5, lane = tid & 31;
    const int bx = blockIdx.x;
    const bool outm = (bx >= ngate);
    int mt, nt;
    const __nv_bfloat16 *Bh_g, *Bl_g;
    if (outm) { mt = bx - ngate; nt = 0; Bh_g = g_Fwh; Bl_g = g_Fwl; }
    else {
        mt = bx >> 4; nt = bx & 15;
        Bh_g = (use0 ? g_G0h : g_Gh) + nt * 128 * Hsz;
        Bl_g = (use0 ? g_G0l : g_Gl) + nt * 128 * Hsz;
    }
    const __nv_bfloat16* Ah_g = g_Ah[pp] + mt * 128 * Hsz;
    const __nv_bfloat16* Al_g = g_Al[pp] + mt * 128 * Hsz;

    // copy mapping: thread -> row cr, 4 consecutive 16B units starting cu0
    const int cr = tid >> 1;
    const int cu0 = (tid & 1) * 4;
    const int crx = cr & 7;
    const uint32_t srow = cr * 128;

    #define LOAD_STAGE(c, st) do {                                             \
        const int koff = (c) * 64;                                             \
        const uint32_t stb = sb + (st) * STG;                                  \
        _Pragma("unroll")                                                      \
        for (int j = 0; j < 4; j++) {                                          \
            const int u = cu0 + j;                                             \
            const uint32_t so = srow + (((u) ^ crx) << 4);                     \
            const int go = cr * Hsz + koff + u * 8;                            \
            cpa16(stb +         so, Ah_g + go);                                \
            cpa16(stb + 16384 + so, Al_g + go);                                \
            cpa16(stb + 32768 + so, Bh_g + go);                                \
            cpa16(stb + 49152 + so, Bl_g + go);                                \
        }                                                                      \
        cpa_commit();                                                          \
    } while (0)

    // ldmatrix addressing
    const int wm0 = (wid >> 2) * 64;
    const int wn0 = (wid & 3) * 32;
    const int r15 = lane & 15;
    const int xr = lane & 7;
    const int ub = lane >> 4;
    uint32_t arow[4], brow[2];
    #pragma unroll
    for (int mb = 0; mb < 4; mb++) arow[mb] = (wm0 + mb * 16 + r15) * 128;
    #pragma unroll
    for (int np = 0; np < 2; np++) brow[np] = 32768u + (wn0 + np * 16 + r15) * 128;

    float acc[4][4][4];
    #pragma unroll
    for (int a = 0; a < 4; a++)
        #pragma unroll
        for (int b = 0; b < 4; b++)
            #pragma unroll
            for (int cc = 0; cc < 4; cc++) acc[a][b][cc] = 0.f;

    LOAD_STAGE(0, 0);
    LOAD_STAGE(1, 1);

    for (int c = 0; c < NCHUNK; c++) {
        cpa_wait1();
        __syncthreads();
        if (c + 2 < NCHUNK) LOAD_STAGE(c + 2, (c + 2) % 3);
        const uint32_t base = sb + (c % 3) * STG;
        #pragma unroll
        for (int kk = 0; kk < 4; kk++) {
            const uint32_t up = (uint32_t)(((kk * 2 + ub) ^ xr) << 4);
            uint32_t ah[4][4], al[4][4];
            #pragma unroll
            for (int mb = 0; mb < 4; mb++) {
                ldm4(ah[mb], base + arow[mb] + up);
                ldm4(al[mb], base + 16384 + arow[mb] + up);
            }
            #pragma unroll
            for (int np = 0; np < 2; np++) {
                uint32_t bh[4], bl[4];
                ldm4(bh, base + brow[np] + up);
                ldm4(bl, base + 16384 + brow[np] + up);
                #pragma unroll
                for (int mb = 0; mb < 4; mb++) {
                    float* a0 = acc[mb][np * 2 + 0];
                    float* a1 = acc[mb][np * 2 + 1];
                    mma_bf16(a0, ah[mb], bh[0], bh[2]);
                    mma_bf16(a0, al[mb], bh[0], bh[2]);
                    mma_bf16(a0, ah[mb], bl[0], bl[2]);
                    mma_bf16(a1, ah[mb], bh[1], bh[3]);
                    mma_bf16(a1, al[mb], bh[1], bh[3]);
                    mma_bf16(a1, ah[mb], bl[1], bl[3]);
                }
            }
        }
    }

    // ---- epilogue ----
    const int trow = lane >> 2, q = lane & 3, qp = q & 1;
    if (!outm) {
        const float* __restrict__ bias = use0 ? g_bias0 : g_bias;
        const float* __restrict__ hfin = g_hf[pp];
        float* __restrict__ hfout = g_hf[pp ^ 1];
        __nv_bfloat16* aoh = g_Ah[pp ^ 1];
        __nv_bfloat16* aol = g_Al[pp ^ 1];
        #pragma unroll
        for (int mb = 0; mb < 4; mb++) {
            #pragma unroll
            for (int nb = 0; nb < 4; nb++) {
                float c0 = acc[mb][nb][0], c1 = acc[mb][nb][1];
                float c2 = acc[mb][nb][2], c3 = acc[mb][nb][3];
                float rx0 = __shfl_xor_sync(0xffffffffu, c0, 1);
                float rx1 = __shfl_xor_sync(0xffffffffu, c1, 1);
                float rx2 = __shfl_xor_sync(0xffffffffu, c2, 1);
                float rx3 = __shfl_xor_sync(0xffffffffu, c3, 1);
                const int nbase = nt * 128 + wn0 + nb * 8 + (q >> 1) * 4;
                const int j = nbase >> 2;
                const float4 bq = *(const float4*)(bias + nbase);
                const int row = mt * 128 + wm0 + mb * 16 + trow + (qp ? 8 : 0);
                float pr, pz, pn, ph;
                if (qp == 0) { pr = c0 + bq.x; pz = c1 + bq.y; pn = rx0 + bq.z; ph = rx1 + bq.w; }
                else         { pr = rx2 + bq.x; pz = rx3 + bq.y; pn = c2 + bq.z; ph = c3 + bq.w; }
                float rg = 1.f / (1.f + __expf(-pr));
                float zg = 1.f / (1.f + __expf(-pz));
                float ng = tanhf(pn + rg * ph);
                float hold = hfin[row * Hsz + j];
                float hn = (1.f - zg) * ng + zg * hold;
                const int o = row * Hsz + j;
                hfout[o] = hn;
                put_split(aoh, aol, o, hn);
            }
        }
    } else {
        #pragma unroll
        for (int mb = 0; mb < 4; mb++) {
            #pragma unroll
            for (int nb = 0; nb < 4; nb++) {
                const int f = wn0 + nb * 8 + 2 * q;
                const int r0 = mt * 128 + wm0 + mb * 16 + trow;
                const float b0 = fcb[f], b1 = fcb[f + 1];
                float* p0 = outp + (size_t)r0 * (Tsz * Fsz) + (size_t)tout * Fsz + f;
                float* p1 = p0 + 8 * (Tsz * Fsz);
                p0[0] = acc[mb][nb][0] + b0; p0[1] = acc[mb][nb][1] + b1;
                p1[0] = acc[mb][nb][2] + b0; p1[1] = acc[mb][nb][3] + b1;
            }
        }
    }
    #undef LOAD_STAGE
}

extern "C" void kernel_launch(void* const* d_in, const int* in_sizes, int n_in,
                              void* d_out, int out_size) {
    (void)in_sizes; (void)n_in; (void)out_size;
    const float* hidden = (const float*)d_in[0];
    const float* w_ih   = (const float*)d_in[1];
    const float* w_hh   = (const float*)d_in[2];
    const float* b_ih   = (const float*)d_in[3];
    const float* b_hh   = (const float*)d_in[4];
    const float* fc_w   = (const float*)d_in[5];
    const float* fc_b   = (const float*)d_in[6];
    float* outp = (float*)d_out;

    cudaFuncSetAttribute(mma_step, cudaFuncAttributeMaxDynamicSharedMemorySize, SMEMB);

    conv_h0_kernel<<<(Bsz * Hsz) / 256, 256>>>(hidden);
    precompute_kernel<<<3 * Hsz, Hsz>>>(w_ih, w_hh, b_ih, b_hh, fc_w, fc_b);
    conv_fw_kernel<<<(Fsz * Hsz) / 256, 256>>>(fc_w);

    // step 0: x=0 weights (G0), no fused output
    mma_step<<<256, 256, SMEMB>>>(0, 1, 256, 0, fc_b, outp);
    // steps 1..95: gate GEMM for step t + output of step t-1 (row 96-t)
    for (int t = 1; t < Tsz; t++)
        mma_step<<<272, 256, SMEMB>>>(t & 1, 0, 256, Tsz - t, fc_b, outp);
    // final output from h_96 (parity 0), row 0
    mma_step<<<16, 256, SMEMB>>>(0, 0, 0, 0, fc_b, outp);
}

// round 5
// speedup vs baseline: 1.8313x; 1.2963x over previous
#include <cuda_runtime.h>
#include <cuda_bf16.h>
#include <math.h>
#include <stdint.h>

// GRU decoder B=2048,H=512,F=128,T=96 via mma.sync bf16 HMMA (fp32 acc).
// One folded GEMM per step: C = h_t @ G^T, G packed (N=2048,K=512),
// col n=4j+g: [r_comb, z_comb, i_n, h_n]; fp32 via 3-term bf16 split.
// R5: BM=256,BN=128,BK=64, 512 threads (16 warps), 2-stage pipeline,
// one-wave grid (136 CTAs/step incl. fused output GEMM).

#define Bsz 2048
#define Hsz 512
#define Fsz 128
#define Tsz 96
#define NCHUNK 8            // K=512 / BK=64
#define STG 98304           // Ah 32K | Al 32K | Bh 16K | Bl 16K
#define SMEMB (2 * STG)     // 192KB

__device__ __nv_bfloat16 g_Gh [2048 * 512];
__device__ __nv_bfloat16 g_Gl [2048 * 512];
__device__ __nv_bfloat16 g_G0h[2048 * 512];
__device__ __nv_bfloat16 g_G0l[2048 * 512];
__device__ __nv_bfloat16 g_Fwh[128 * 512];
__device__ __nv_bfloat16 g_Fwl[128 * 512];
__device__ __nv_bfloat16 g_Ah[2][2048 * 512];
__device__ __nv_bfloat16 g_Al[2][2048 * 512];
__device__ float g_hf[2][2048 * 512];
__device__ float g_bias[2048];
__device__ float g_bias0[2048];

__device__ __forceinline__ uint32_t smem_u32(const void* p) {
    uint32_t a;
    asm("{ .reg .u64 t; cvta.to.shared.u64 t, %1; cvt.u32.u64 %0, t; }" : "=r"(a) : "l"(p));
    return a;
}
__device__ __forceinline__ void mma_bf16(float* d, const uint32_t* a, uint32_t b0, uint32_t b1) {
    asm volatile(
        "mma.sync.aligned.m16n8k16.row.col.f32.bf16.bf16.f32 "
        "{%0,%1,%2,%3}, {%4,%5,%6,%7}, {%8,%9}, {%0,%1,%2,%3};"
        : "+f"(d[0]), "+f"(d[1]), "+f"(d[2]), "+f"(d[3])
        : "r"(a[0]), "r"(a[1]), "r"(a[2]), "r"(a[3]), "r"(b0), "r"(b1));
}
__device__ __forceinline__ void ldm4(uint32_t* r, uint32_t addr) {
    asm volatile("ldmatrix.sync.aligned.m8n8.x4.shared.b16 {%0,%1,%2,%3}, [%4];"
                 : "=r"(r[0]), "=r"(r[1]), "=r"(r[2]), "=r"(r[3]) : "r"(addr));
}
__device__ __forceinline__ void cpa16(uint32_t s, const void* g) {
    asm volatile("cp.async.cg.shared.global [%0], [%1], 16;" :: "r"(s), "l"(g));
}
__device__ __forceinline__ void cpa_commit() { asm volatile("cp.async.commit_group;" ::: "memory"); }
__device__ __forceinline__ void cpa_wait1()  { asm volatile("cp.async.wait_group 1;"  ::: "memory"); }
__device__ __forceinline__ void cpa_wait0()  { asm volatile("cp.async.wait_group 0;"  ::: "memory"); }

__device__ __forceinline__ void put_split(__nv_bfloat16* H, __nv_bfloat16* L, int idx, float v) {
    __nv_bfloat16 h = __float2bfloat16(v);
    __nv_bfloat16 l = __float2bfloat16(v - __bfloat162float(h));
    H[idx] = h; L[idx] = l;
}

__global__ void precompute_kernel(const float* __restrict__ w_ih,
                                  const float* __restrict__ w_hh,
                                  const float* __restrict__ b_ih,
                                  const float* __restrict__ b_hh,
                                  const float* __restrict__ fc_w,
                                  const float* __restrict__ fc_b) {
    int r = blockIdx.x;   // 0..1535
    int k = threadIdx.x;  // 0..511
    __shared__ float sw[Fsz], sb[Fsz];
    if (k < Fsz) { sw[k] = w_ih[r * Fsz + k]; sb[k] = fc_b[k]; }
    __syncthreads();
    float acc = 0.f;
    #pragma unroll 8
    for (int f = 0; f < Fsz; f++) acc += sw[f] * fc_w[f * Hsz + k];
    float whh = w_hh[r * Hsz + k];
    int j = r & (Hsz - 1);
    int band = r >> 9;
    if (band == 0) {
        int o = (4 * j + 0) * Hsz + k;
        put_split(g_Gh, g_Gl, o, acc + whh);
        put_split(g_G0h, g_G0l, o, whh);
    } else if (band == 1) {
        int o = (4 * j + 1) * Hsz + k;
        put_split(g_Gh, g_Gl, o, acc + whh);
        put_split(g_G0h, g_G0l, o, whh);
    } else {
        int o2 = (4 * j + 2) * Hsz + k;
        put_split(g_Gh, g_Gl, o2, acc);
        put_split(g_G0h, g_G0l, o2, 0.f);
        int o3 = (4 * j + 3) * Hsz + k;
        put_split(g_Gh, g_Gl, o3, whh);
        put_split(g_G0h, g_G0l, o3, whh);
    }
    if (k == 0) {
        float b2 = 0.f;
        for (int f = 0; f < Fsz; f++) b2 += sw[f] * sb[f];
        float bih = b_ih[r], bhh = b_hh[r];
        if (band == 0) { g_bias[4*j+0] = b2 + bih + bhh; g_bias0[4*j+0] = bih + bhh; }
        else if (band == 1) { g_bias[4*j+1] = b2 + bih + bhh; g_bias0[4*j+1] = bih + bhh; }
        else {
            g_bias [4*j+2] = b2 + bih;  g_bias0[4*j+2] = bih;
            g_bias [4*j+3] = bhh;       g_bias0[4*j+3] = bhh;
        }
    }
}

__global__ void conv_fw_kernel(const float* __restrict__ fc_w) {
    int idx = blockIdx.x * blockDim.x + threadIdx.x;
    put_split(g_Fwh, g_Fwl, idx, fc_w[idx]);
}

__global__ void conv_h0_kernel(const float* __restrict__ hidden) {
    int idx = blockIdx.x * blockDim.x + threadIdx.x;
    float v = hidden[idx];
    g_hf[0][idx] = v;
    put_split(g_Ah[0], g_Al[0], idx, v);
}

// ---- fused step kernel: BM=256, BN=128, BK=64, 512 threads (16 warps 4x4) ----
// gate CTAs: mt = bx>>4 (8 M-tiles), nt = bx&15 (16 N-tiles).
// out  CTAs: mt = bx-ngate, B = fc_w (exactly one 128-row tile).
__global__ __launch_bounds__(512, 1)
void mma_step(int pp, int use0, int ngate, int tout,
              const float* __restrict__ fcb, float* __restrict__ outp) {
    extern __shared__ unsigned char smraw[];
    const uint32_t sb = smem_u32(smraw);

    const int tid = threadIdx.x, wid = tid >> 5, lane = tid & 31;
    const int bx = blockIdx.x;
    const bool outm = (bx >= ngate);
    int mt, nt;
    const __nv_bfloat16 *Bh_g, *Bl_g;
    if (outm) { mt = bx - ngate; nt = 0; Bh_g = g_Fwh; Bl_g = g_Fwl; }
    else {
        mt = bx >> 4; nt = bx & 15;
        Bh_g = (use0 ? g_G0h : g_Gh) + nt * 128 * Hsz;
        Bl_g = (use0 ? g_G0l : g_Gl) + nt * 128 * Hsz;
    }
    const __nv_bfloat16* Ah_g = g_Ah[pp] + mt * 256 * Hsz;
    const __nv_bfloat16* Al_g = g_Al[pp] + mt * 256 * Hsz;

    // stage copy: A 2048 16B-units (4/thread), B 1024 units (2/thread), hi+lo
    #define LOAD_STAGE(c, st) do {                                              \
        const int koff = (c) * 64;                                              \
        const uint32_t stb = sb + (st) * STG;                                   \
        _Pragma("unroll")                                                       \
        for (int j = 0; j < 4; j++) {                                           \
            const int u = tid + j * 512;                                        \
            const int row = u >> 3, un = u & 7;                                 \
            const uint32_t so = row * 128 + (uint32_t)((un ^ (row & 7)) << 4);  \
            const int go = row * Hsz + koff + un * 8;                           \
            cpa16(stb +         so, Ah_g + go);                                 \
            cpa16(stb + 32768 + so, Al_g + go);                                 \
            if (j < 2) {                                                        \
                cpa16(stb + 65536 + so, Bh_g + go);                             \
                cpa16(stb + 81920 + so, Bl_g + go);                             \
            }                                                                   \
        }                                                                       \
        cpa_commit();                                                           \
    } while (0)

    const int wm0 = (wid >> 2) * 64;     // 0,64,128,192
    const int wn0 = (wid & 3) * 32;      // 0,32,64,96
    const int r15 = lane & 15;
    const int xr = lane & 7;
    const int ub = lane >> 4;
    uint32_t arow[4], brow[2];
    #pragma unroll
    for (int mb = 0; mb < 4; mb++) arow[mb] = (wm0 + mb * 16 + r15) * 128;
    #pragma unroll
    for (int np = 0; np < 2; np++) brow[np] = (wn0 + np * 16 + r15) * 128;

    float acc[4][4][4];
    #pragma unroll
    for (int a = 0; a < 4; a++)
        #pragma unroll
        for (int b = 0; b < 4; b++)
            #pragma unroll
            for (int cc = 0; cc < 4; cc++) acc[a][b][cc] = 0.f;

    LOAD_STAGE(0, 0);

    for (int c = 0; c < NCHUNK; c++) {
        if (c + 1 < NCHUNK) { LOAD_STAGE(c + 1, (c + 1) & 1); cpa_wait1(); }
        else cpa_wait0();
        __syncthreads();
        const uint32_t base = sb + (c & 1) * STG;
        #pragma unroll
        for (int kk = 0; kk < 4; kk++) {
            const uint32_t up = (uint32_t)(((kk * 2 + ub) ^ xr) << 4);
            uint32_t bh[2][4], bl[2][4];
            #pragma unroll
            for (int np = 0; np < 2; np++) {
                ldm4(bh[np], base + 65536 + brow[np] + up);
                ldm4(bl[np], base + 81920 + brow[np] + up);
            }
            #pragma unroll
            for (int mb = 0; mb < 4; mb++) {
                uint32_t ah[4], al[4];
                ldm4(ah, base + arow[mb] + up);
                ldm4(al, base + 32768 + arow[mb] + up);
                #pragma unroll
                for (int np = 0; np < 2; np++) {
                    float* a0 = acc[mb][np * 2 + 0];
                    float* a1 = acc[mb][np * 2 + 1];
                    mma_bf16(a0, ah, bh[np][0], bh[np][2]);
                    mma_bf16(a0, al, bh[np][0], bh[np][2]);
                    mma_bf16(a0, ah, bl[np][0], bl[np][2]);
                    mma_bf16(a1, ah, bh[np][1], bh[np][3]);
                    mma_bf16(a1, al, bh[np][1], bh[np][3]);
                    mma_bf16(a1, ah, bl[np][1], bl[np][3]);
                }
            }
        }
        __syncthreads();   // protect buffer (c&1) before next-next load
    }

    // ---- epilogue ----
    const int trow = lane >> 2, q = lane & 3, qp = q & 1;
    if (!outm) {
        const float* __restrict__ bias = use0 ? g_bias0 : g_bias;
        const float* __restrict__ hfin = g_hf[pp];
        float* __restrict__ hfout = g_hf[pp ^ 1];
        __nv_bfloat16* aoh = g_Ah[pp ^ 1];
        __nv_bfloat16* aol = g_Al[pp ^ 1];
        #pragma unroll
        for (int mb = 0; mb < 4; mb++) {
            #pragma unroll
            for (int nb = 0; nb < 4; nb++) {
                float c0 = acc[mb][nb][0], c1 = acc[mb][nb][1];
                float c2 = acc[mb][nb][2], c3 = acc[mb][nb][3];
                float rx0 = __shfl_xor_sync(0xffffffffu, c0, 1);
                float rx1 = __shfl_xor_sync(0xffffffffu, c1, 1);
                float rx2 = __shfl_xor_sync(0xffffffffu, c2, 1);
                float rx3 = __shfl_xor_sync(0xffffffffu, c3, 1);
                const int nbase = nt * 128 + wn0 + nb * 8 + (q >> 1) * 4;
                const int j = nbase >> 2;
                const float4 bq = *(const float4*)(bias + nbase);
                const int row = mt * 256 + wm0 + mb * 16 + trow + (qp ? 8 : 0);
                float pr, pz, pn, ph;
                if (qp == 0) { pr = c0 + bq.x; pz = c1 + bq.y; pn = rx0 + bq.z; ph = rx1 + bq.w; }
                else         { pr = rx2 + bq.x; pz = rx3 + bq.y; pn = c2 + bq.z; ph = c3 + bq.w; }
                float rg = 1.f / (1.f + __expf(-pr));
                float zg = 1.f / (1.f + __expf(-pz));
                float ng = tanhf(pn + rg * ph);
                float hold = hfin[row * Hsz + j];
                float hn = (1.f - zg) * ng + zg * hold;
                const int o = row * Hsz + j;
                hfout[o] = hn;
                put_split(aoh, aol, o, hn);
            }
        }
    } else {
        #pragma unroll
        for (int mb = 0; mb < 4; mb++) {
            #pragma unroll
            for (int nb = 0; nb < 4; nb++) {
                const int f = wn0 + nb * 8 + 2 * q;
                const int r0 = mt * 256 + wm0 + mb * 16 + trow;
                const float b0 = fcb[f], b1 = fcb[f + 1];
                float* p0 = outp + (size_t)r0 * (Tsz * Fsz) + (size_t)tout * Fsz + f;
                float* p1 = p0 + 8 * (Tsz * Fsz);
                p0[0] = acc[mb][nb][0] + b0; p0[1] = acc[mb][nb][1] + b1;
                p1[0] = acc[mb][nb][2] + b0; p1[1] = acc[mb][nb][3] + b1;
            }
        }
    }
    #undef LOAD_STAGE
}

extern "C" void kernel_launch(void* const* d_in, const int* in_sizes, int n_in,
                              void* d_out, int out_size) {
    (void)in_sizes; (void)n_in; (void)out_size;
    const float* hidden = (const float*)d_in[0];
    const float* w_ih   = (const float*)d_in[1];
    const float* w_hh   = (const float*)d_in[2];
    const float* b_ih   = (const float*)d_in[3];
    const float* b_hh   = (const float*)d_in[4];
    const float* fc_w   = (const float*)d_in[5];
    const float* fc_b   = (const float*)d_in[6];
    float* outp = (float*)d_out;

    cudaFuncSetAttribute(mma_step, cudaFuncAttributeMaxDynamicSharedMemorySize, SMEMB);

    conv_h0_kernel<<<(Bsz * Hsz) / 256, 256>>>(hidden);
    precompute_kernel<<<3 * Hsz, Hsz>>>(w_ih, w_hh, b_ih, b_hh, fc_w, fc_b);
    conv_fw_kernel<<<(Fsz * Hsz) / 256, 256>>>(fc_w);

    // step 0: x=0 weights (G0), no fused output
    mma_step<<<128, 512, SMEMB>>>(0, 1, 128, 0, fc_b, outp);
    // steps 1..95: gate GEMM for step t + output of step t-1 (row 96-t)
    for (int t = 1; t < Tsz; t++)
        mma_step<<<136, 512, SMEMB>>>(t & 1, 0, 128, Tsz - t, fc_b, outp);
    // final output from h_96 (parity 0), row 0
    mma_step<<<8, 512, SMEMB>>>(0, 0, 0, 0, fc_b, outp);
}